// round 13
// baseline (speedup 1.0000x reference)
#include <cuda_runtime.h>
#include <cuda_fp16.h>
#include <cstdint>

// Problem constants
#define B_   32
#define C_   128
#define H_   64
#define W_   64
#define O_   256
#define K_   1152            // C*9 (reordered: k' = r*128 + c, r = kh*3+kw)
#define M_   32768

// Permuted fp16 weights: g_wb[o][r*128 + c] = w[o][c*9 + r]
__device__ __half g_wb[O_ * K_];

// ---------------------------------------------------------------------------
// Kernel 1: weight permute+convert. idx = o*1152 + r*128 + c (coalesced write)
// ---------------------------------------------------------------------------
__global__ void wperm_kernel(const float* __restrict__ w)
{
    int idx = blockIdx.x * blockDim.x + threadIdx.x;   // 0 .. 294911
    int c  = idx & 127;
    int t2 = idx >> 7;        // o*9 + r
    int r  = t2 % 9;
    int o  = t2 / 9;
    g_wb[idx] = __float2half_rn(__ldg(w + o * K_ + c * 9 + r));
}

// ---------------------------------------------------------------------------
// Kernel 2: FUSED im2col + GEMM.
//   CTA: 512 threads, m-tile 64 (1 batch, 2 p-rows, 32 q), full N=256.
//   smem: xsm fp16 [8h][68w][130c] (141.4KB) + A dbuf 2x8KB + B dbuf 2x32KB.
//   Mainloop: produce A[it+1] (bilinear from xsm) while mma(A[it], B[it]).
// ---------------------------------------------------------------------------
#define NK 18                        // K chunks of 64
#define XSM_HALVES (8 * 68 * 130)    // 70720 halves = 141440 B
#define ABUF_OFF  141440
#define ABUF_SZ   8192               // 64 m x 128 B
#define BBUF_OFF  (ABUF_OFF + 2 * ABUF_SZ)      // 157824
#define BBUF_SZ   32768              // 256 o x 128 B
#define SMEM_TOTAL (BBUF_OFF + 2 * BBUF_SZ)     // 223360

#define SWO(row, chunk) ((uint32_t)((row) * 128 + (((chunk) ^ ((row) & 7)) << 4)))

__device__ __forceinline__ uint32_t cvta_s(const void* p)
{
    uint32_t a;
    asm("{ .reg .u64 t; cvta.to.shared.u64 t, %1; cvt.u32.u64 %0, t; }"
        : "=r"(a) : "l"(p));
    return a;
}

__device__ __forceinline__ void cp16(uint32_t s, const void* g)
{
    asm volatile("cp.async.ca.shared.global [%0], [%1], 16;"
                 :: "r"(s), "l"(g));
}

__device__ __forceinline__ void ldsm4(uint32_t a, uint32_t* r)
{
    asm volatile("ldmatrix.sync.aligned.m8n8.x4.shared.b16 {%0,%1,%2,%3}, [%4];"
                 : "=r"(r[0]), "=r"(r[1]), "=r"(r[2]), "=r"(r[3]) : "r"(a));
}

__device__ __forceinline__ void mma16816(float* d, const uint32_t* a,
                                         const uint32_t* b)
{
    asm volatile(
        "mma.sync.aligned.m16n8k16.row.col.f32.f16.f16.f32 "
        "{%0,%1,%2,%3}, {%4,%5,%6,%7}, {%8,%9}, {%0,%1,%2,%3};"
        : "+f"(d[0]), "+f"(d[1]), "+f"(d[2]), "+f"(d[3])
        : "r"(a[0]), "r"(a[1]), "r"(a[2]), "r"(a[3]), "r"(b[0]), "r"(b[1]));
}

__global__ __launch_bounds__(512, 1)
void fused_kernel(const float* __restrict__ x,
                  const float* __restrict__ bias,
                  const float* __restrict__ sh_p,
                  const float* __restrict__ sw_p,
                  float* __restrict__ out)
{
    extern __shared__ char smem[];
    __half* xsm = (__half*)smem;
    const uint32_t sbase = cvta_s(smem);

    const int tid  = threadIdx.x;
    const int lane = tid & 31;
    const int wid  = tid >> 5;

    const int b   = blockIdx.x >> 4;             // batch
    const int p0  = (blockIdx.x & 15) << 1;      // first of 2 p-rows (even)
    const int pq0 = (blockIdx.x & 15) * 64;      // pq offset within batch

    const float sh = __ldg(sh_p);
    const float sw = __ldg(sw_p);

    const float ph0f = (float)p0 * sh - 1.0f;
    const int hbase  = (int)floorf(ph0f);

    // ---- B loader mapping: 2048 16B chunks / 512 thr -> 4 each ----
    const int rowB = tid >> 1;                 // 0..255
    const int cB0  = (tid & 1) * 4;
    const char* gB = (const char*)g_wb + (size_t)rowB * K_ * 2;

#define LOAD_B(stage, buf)                                                     \
    {                                                                          \
        const uint32_t sb = sbase + BBUF_OFF + (buf) * BBUF_SZ;                \
        const size_t gk = (size_t)(stage) * 128;                               \
        _Pragma("unroll")                                                      \
        for (int ci = 0; ci < 4; ci++)                                         \
            cp16(sb + SWO(rowB, cB0 + ci), gB + gk + (cB0 + ci) * 16);         \
    }

    // start B transfers immediately (overlap with x staging)
    LOAD_B(0, 0);
    asm volatile("cp.async.commit_group;");
    LOAD_B(1, 1);
    asm volatile("cp.async.commit_group;");

    // ---- zero xsm (boundary slots/rows must read 0) ----
    {
        uint4 z = make_uint4(0, 0, 0, 0);
        uint4* xz = (uint4*)smem;
        for (int i = tid; i < XSM_HALVES / 8; i += 512) xz[i] = z;
    }
    __syncthreads();

    // ---- stage x rows hbase..hbase+7 as fp16 [h][wslot=w+1][c pad130] ----
    {
        const float4* xg = (const float4*)x;
        for (int r8 = 0; r8 < 8; r8++) {
            const int hh = hbase + r8;
            if ((unsigned)hh < (unsigned)H_) {
                for (int i = tid; i < 2048; i += 512) {
                    const int c  = i >> 4;
                    const int w4 = i & 15;
                    float4 v = xg[((size_t)(b * C_ + c) * H_ + hh) * 16 + w4];
                    const int base = (r8 * 68 + w4 * 4 + 1) * 130 + c;
                    xsm[base]           = __float2half_rn(v.x);
                    xsm[base + 130]     = __float2half_rn(v.y);
                    xsm[base + 260]     = __float2half_rn(v.z);
                    xsm[base + 390]     = __float2half_rn(v.w);
                }
            }
        }
    }
    __syncthreads();

    // ---- per-thread A-production constants (m = tid>>3, 8 channels) ----
    const int m_loc = tid >> 3;                 // 0..63
    const int cbase = (tid & 7) * 8;            // 8 consecutive channels
    const int qq = m_loc & 31;
    const int pl = m_loc >> 5;
    const float php = (float)(p0 + pl) * sh - 1.0f;
    const float fhp = floorf(php);
    const float ah  = php - fhp;
    int hoff = (int)fhp - hbase; if (hoff < 0) hoff = 0; if (hoff > 4) hoff = 4;
    const float pwq = (float)qq * sw - 1.0f;
    const float fwq = floorf(pwq);
    const float aw  = pwq - fwq;
    const int wsb   = (int)fwq + 1;             // wslot of w0

    auto produce = [&](int rn, char* adst) {
        const int rr  = rn >> 1;                // tap index 0..8
        const int cc0 = (rn & 1) << 6;          // channel half
        const int kh  = rr / 3;
        const int kw  = rr - kh * 3;
        int rt = hoff + kh; if (rt > 6) rt = 6;
        const int ws  = wsb + kw;
        const int ws0 = (ws  < 67) ? ws  : 67;   // slots 65..67 are zero pad
        const int ws1 = (ws + 1 < 67) ? ws + 1 : 67;
        const int ci  = cc0 + cbase;
        const __half* p00 = xsm + (rt * 68 + ws0) * 130 + ci;
        const __half* p01 = xsm + (rt * 68 + ws1) * 130 + ci;
        const __half* p10 = p00 + 68 * 130;
        const __half* p11 = p01 + 68 * 130;
        uint32_t res[4];
#pragma unroll
        for (int j = 0; j < 4; j++) {
            float2 f00 = __half22float2(*(const __half2*)(p00 + 2 * j));
            float2 f01 = __half22float2(*(const __half2*)(p01 + 2 * j));
            float2 f10 = __half22float2(*(const __half2*)(p10 + 2 * j));
            float2 f11 = __half22float2(*(const __half2*)(p11 + 2 * j));
            float tx = f00.x + (f01.x - f00.x) * aw;
            float ty = f00.y + (f01.y - f00.y) * aw;
            float bx = f10.x + (f11.x - f10.x) * aw;
            float by = f10.y + (f11.y - f10.y) * aw;
            __half2 hv = __floats2half2_rn(tx + (bx - tx) * ah,
                                           ty + (by - ty) * ah);
            res[j] = *(uint32_t*)&hv;
        }
        *(uint4*)(adst + m_loc * 128 + ((((uint32_t)(tid & 7)) ^ (m_loc & 7)) << 4))
            = make_uint4(res[0], res[1], res[2], res[3]);
    };

    // prologue: produce A[0]
    produce(0, smem + ABUF_OFF);

    // ---- MMA mapping: 16 warps = 2(m) x 8(n); warp tile 32m x 32n ----
    const int wm = (wid & 1) * 32;
    const int wn = (wid >> 1) * 32;
    const int a_row  = lane & 15;
    const int a_col8 = lane >> 4;
    const int b_row  = (lane & 7) + ((lane >> 4) << 3);
    const int b_col8 = (lane >> 3) & 1;

    float acc[2][4][4];
#pragma unroll
    for (int i = 0; i < 2; i++)
#pragma unroll
        for (int j = 0; j < 4; j++)
#pragma unroll
            for (int r = 0; r < 4; r++) acc[i][j][r] = 0.0f;

    for (int it = 0; it < NK; it++) {
        asm volatile("cp.async.wait_group 1;");
        __syncthreads();   // A[it] (produced last iter) + B[it] visible

        // produce next A chunk (issues on fma/lsu while tensor pipe works)
        if (it + 1 < NK)
            produce(it + 1, smem + ABUF_OFF + ((it + 1) & 1) * ABUF_SZ);

        const uint32_t sA = sbase + ABUF_OFF + (it & 1) * ABUF_SZ;
        const uint32_t sB = sbase + BBUF_OFF + (it & 1) * BBUF_SZ;

#pragma unroll
        for (int ks = 0; ks < 4; ks++) {
            uint32_t a[2][4], bfr[2][4];
#pragma unroll
            for (int i = 0; i < 2; i++)
                ldsm4(sA + SWO(wm + i * 16 + a_row, 2 * ks + a_col8), a[i]);
#pragma unroll
            for (int j2 = 0; j2 < 2; j2++)
                ldsm4(sB + SWO(wn + j2 * 16 + b_row, 2 * ks + b_col8), bfr[j2]);
#pragma unroll
            for (int i = 0; i < 2; i++)
#pragma unroll
                for (int j = 0; j < 4; j++)
                    mma16816(acc[i][j], a[i], &bfr[j >> 1][(j & 1) * 2]);
        }

        __syncthreads();   // all reads of Bbuf[it&1] done before refill
        if (it + 2 < NK) LOAD_B(it + 2, it & 1);
        asm volatile("cp.async.commit_group;");   // one commit per iter
    }

    asm volatile("cp.async.wait_group 0;");
    __syncthreads();

    // ---- epilogue: four 64-o quarters via smem transpose (reuses xsm area) ----
    // row stride 68 floats = 272 B = 17*16 -> float4-aligned for every row.
    float* eb = (float*)smem;            // [64 o][68 m] floats = 17.4 KB

#pragma unroll
    for (int h = 0; h < 4; h++) {
        const int oh0 = h * 64;
        if (wn >= oh0 && wn < oh0 + 64) {
#pragma unroll
            for (int i = 0; i < 2; i++) {
                int ml = wm + i * 16 + (lane >> 2);
#pragma unroll
                for (int j = 0; j < 4; j++) {
                    int ol = wn - oh0 + j * 8 + (lane & 3) * 2;
                    eb[ol * 68 + ml]           = acc[i][j][0];
                    eb[(ol + 1) * 68 + ml]     = acc[i][j][1];
                    eb[ol * 68 + ml + 8]       = acc[i][j][2];
                    eb[(ol + 1) * 68 + ml + 8] = acc[i][j][3];
                }
            }
        }
        __syncthreads();

        // 512 threads store 64 o x 64 m: 8 floats each
        const int oo  = tid >> 3;            // 0..63
        const int oct = tid & 7;             // 8 m each
        const int og  = oh0 + oo;
        const float bv = __ldg(bias + og);
        float* op = out + (size_t)b * (O_ * 1024)
                  + (size_t)og * 1024 + pq0 + oct * 8;
        const float* sp = eb + oo * 68 + oct * 8;
        float4 v0 = *(const float4*)(sp);
        float4 v1 = *(const float4*)(sp + 4);
        v0.x += bv; v0.y += bv; v0.z += bv; v0.w += bv;
        v1.x += bv; v1.y += bv; v1.z += bv; v1.w += bv;
        *(float4*)(op)     = v0;
        *(float4*)(op + 4) = v1;
        __syncthreads();
    }
#undef LOAD_B
}

// ---------------------------------------------------------------------------
extern "C" void kernel_launch(void* const* d_in, const int* in_sizes, int n_in,
                              void* d_out, int out_size)
{
    const float* x    = (const float*)d_in[0];
    const float* w    = (const float*)d_in[1];
    const float* bias = (const float*)d_in[2];
    const float* sh   = (const float*)d_in[3];
    const float* sw   = (const float*)d_in[4];
    float* out = (float*)d_out;

    cudaFuncSetAttribute(fused_kernel,
                         cudaFuncAttributeMaxDynamicSharedMemorySize, SMEM_TOTAL);

    wperm_kernel<<<(O_ * K_) / 256, 256>>>(w);
    fused_kernel<<<512, 512, SMEM_TOTAL>>>(x, bias, sh, sw, out);
}

// round 15
// speedup vs baseline: 1.0841x; 1.0841x over previous
#include <cuda_runtime.h>
#include <cuda_fp16.h>
#include <cstdint>

// Problem constants
#define B_   32
#define C_   128
#define H_   64
#define W_   64
#define O_   256
#define K_   1152            // C*9
#define M_   32768           // B*32*32

// Static device scratch
__device__ __half g_pa[(size_t)M_ * K_];   // patches fp16, [m][k]
__device__ __half g_wb[O_ * K_];           // weight fp16,  [o][k]

// ---------------------------------------------------------------------------
// Kernel 1: bilinear im2col, smem-staged, fp16 output (measured-best R7 form).
// ---------------------------------------------------------------------------
#define OUT_STRIDE 292
#define XS_BYTES   32768
#define IM2COL_SMEM (XS_BYTES + 32 * OUT_STRIDE * 2)   // 51456

__global__ __launch_bounds__(256, 4)
void im2col_kernel(const float* __restrict__ x,
                   const float* __restrict__ sh_p,
                   const float* __restrict__ sw_p)
{
    extern __shared__ char sm[];
    float* xs = (float*)sm;                              // [c][4][64]
    __half* ohi = (__half*)(sm + XS_BYTES);              // [32][OUT_STRIDE]

    const int t = threadIdx.x;
    const int b = blockIdx.x >> 5;
    const int p = blockIdx.x & 31;

    const float sh = __ldg(sh_p);
    const float sw = __ldg(sw_p);

    const float ph = (float)p * sh - 1.0f;
    const float fh = floorf(ph);
    const int   h0 = (int)fh;
    const float ah = ph - fh;

    const int q  = t & 31;
    const int cg = t >> 5;
    const float pw = (float)q * sw - 1.0f;
    const float fw = floorf(pw);
    const int   w0 = (int)fw;
    const float aw = pw - fw;

    for (int cc = 0; cc < 4; cc++) {
        const int c0 = cc * 32;

        {
            const float4* xg = (const float4*)x;
            for (int i = t; i < 2048; i += 256) {
                const int cl  = i >> 6;
                const int rem = i & 63;
                const int r   = rem >> 4;
                const int w4  = rem & 15;
                const int hr  = h0 + r;
                float4 v = make_float4(0.f, 0.f, 0.f, 0.f);
                if ((unsigned)hr < (unsigned)H_)
                    v = xg[((size_t)(b * C_ + c0 + cl) * H_ + hr) * 16 + w4];
                ((float4*)xs)[i] = v;
            }
        }
        __syncthreads();

#pragma unroll
        for (int i = 0; i < 4; i++) {
            const int cl = cg * 4 + i;
            const float* xr = xs + cl * 256;

            float v[4][4];
#pragma unroll
            for (int r = 0; r < 4; r++)
#pragma unroll
                for (int j = 0; j < 4; j++) {
                    const int wc = w0 + j;
                    v[r][j] = ((unsigned)wc < (unsigned)W_) ? xr[r * 64 + wc] : 0.0f;
                }

            float cwv[4][3];
#pragma unroll
            for (int r = 0; r < 4; r++)
#pragma unroll
                for (int kw = 0; kw < 3; kw++)
                    cwv[r][kw] = (1.0f - aw) * v[r][kw] + aw * v[r][kw + 1];

            __half* oh = ohi + q * OUT_STRIDE + cl * 9;
#pragma unroll
            for (int kh = 0; kh < 3; kh++)
#pragma unroll
                for (int kw = 0; kw < 3; kw++) {
                    const float val = (1.0f - ah) * cwv[kh][kw] + ah * cwv[kh + 1][kw];
                    oh[kh * 3 + kw] = __float2half_rn(val);
                }
        }
        __syncthreads();

        {
            const size_t mrow = (size_t)(b * 1024 + p * 32);
            for (int i = t; i < 2304; i += 256) {
                const int qq = i / 72;
                const int j  = i - qq * 72;
                const uint2 vh = *(const uint2*)((const char*)ohi + qq * (OUT_STRIDE * 2) + j * 8);
                const size_t gd = ((mrow + qq) * K_ + c0 * 9) * 2 + j * 8;
                *(uint2*)((char*)g_pa + gd) = vh;
            }
        }
        __syncthreads();
    }
}

// ---------------------------------------------------------------------------
// Kernel 2: weight fp32 [o][k] -> fp16 [o][k]
// ---------------------------------------------------------------------------
__global__ void wconv_kernel(const float* __restrict__ w)
{
    int idx = blockIdx.x * blockDim.x + threadIdx.x;
    g_wb[idx] = __float2half_rn(w[idx]);
}

// ---------------------------------------------------------------------------
// Kernel 3: fp16 GEMM, tile D[64m x 256n] per CTA, A read ONCE, 2 CTAs/SM.
//   256 threads, 8 warps (1m x 8n), warp tile 64m x 32n. BK=64, 2 stages
//   (80 KB smem), XOR-swizzled, two syncs per iter (double buffer).
//   grid 512 over 296 slots -> makespan ~= 1.0x of an m128 tile (vs 2 waves).
// ---------------------------------------------------------------------------
#define BK 64
#define NK (K_ / BK)              // 18
#define MATA_BYTES (64 * 128)     // 8 KB
#define MATB_BYTES (256 * 128)    // 32 KB
#define STAGE_BYTES (MATA_BYTES + MATB_BYTES)   // 40960
#define SMEM_BYTES (2 * STAGE_BYTES)            // 81920

#define SWO(row, chunk) ((uint32_t)((row) * 128 + (((chunk) ^ ((row) & 7)) << 4)))

__device__ __forceinline__ uint32_t cvta_s(const void* p)
{
    uint32_t a;
    asm("{ .reg .u64 t; cvta.to.shared.u64 t, %1; cvt.u32.u64 %0, t; }"
        : "=r"(a) : "l"(p));
    return a;
}

__device__ __forceinline__ void cp16(uint32_t s, const void* g)
{
    asm volatile("cp.async.ca.shared.global [%0], [%1], 16;"
                 :: "r"(s), "l"(g));
}

__device__ __forceinline__ void ldsm4(uint32_t a, uint32_t* r)
{
    asm volatile("ldmatrix.sync.aligned.m8n8.x4.shared.b16 {%0,%1,%2,%3}, [%4];"
                 : "=r"(r[0]), "=r"(r[1]), "=r"(r[2]), "=r"(r[3]) : "r"(a));
}

__device__ __forceinline__ void mma16816(float* d, const uint32_t* a,
                                         const uint32_t* b)
{
    asm volatile(
        "mma.sync.aligned.m16n8k16.row.col.f32.f16.f16.f32 "
        "{%0,%1,%2,%3}, {%4,%5,%6,%7}, {%8,%9}, {%0,%1,%2,%3};"
        : "+f"(d[0]), "+f"(d[1]), "+f"(d[2]), "+f"(d[3])
        : "r"(a[0]), "r"(a[1]), "r"(a[2]), "r"(a[3]), "r"(b[0]), "r"(b[1]));
}

__global__ __launch_bounds__(256, 2)
void gemm_kernel(const float* __restrict__ bias, float* __restrict__ out)
{
    extern __shared__ char smem[];
    const uint32_t sbase = cvta_s(smem);

    const int tid  = threadIdx.x;
    const int lane = tid & 31;
    const int wid  = tid >> 5;
    const int m0   = blockIdx.x * 64;

    // loader: per stage A = 512 chunks (2/thr), B = 2048 chunks (8/thr)
    const int rowA = tid >> 2;                 // 0..63
    const int cA0  = (tid & 3) * 2;            // 2 chunks
    const int rowB = tid;                      // 0..255, all 8 chunks
    const char* gA = (const char*)g_pa + ((size_t)(m0 + rowA) * K_) * 2;
    const char* gB = (const char*)g_wb + ((size_t)rowB * K_) * 2;

#define LOAD_STAGE(stage, buf)                                                 \
    {                                                                          \
        const uint32_t sbA = sbase + (buf) * STAGE_BYTES;                      \
        const uint32_t sbB = sbA + MATA_BYTES;                                 \
        const size_t gk = (size_t)(stage) * 128;                               \
        _Pragma("unroll")                                                      \
        for (int ci = 0; ci < 2; ci++)                                         \
            cp16(sbA + SWO(rowA, cA0 + ci), gA + gk + (cA0 + ci) * 16);        \
        _Pragma("unroll")                                                      \
        for (int ci = 0; ci < 8; ci++)                                         \
            cp16(sbB + SWO(rowB, ci), gB + gk + ci * 16);                      \
    }

    // warp grid: 1 (m) x 8 (n); warp tile 64m x 32n
    const int wn = wid * 32;

    const int a_row  = lane & 15;
    const int a_col8 = lane >> 4;
    const int b_row  = (lane & 7) + ((lane >> 4) << 3);
    const int b_col8 = (lane >> 3) & 1;

    float acc[4][4][4];
#pragma unroll
    for (int i = 0; i < 4; i++)
#pragma unroll
        for (int j = 0; j < 4; j++)
#pragma unroll
            for (int r = 0; r < 4; r++) acc[i][j][r] = 0.0f;

    LOAD_STAGE(0, 0);
    asm volatile("cp.async.commit_group;");
    LOAD_STAGE(1, 1);
    asm volatile("cp.async.commit_group;");

    for (int it = 0; it < NK; it++) {
        asm volatile("cp.async.wait_group 1;");
        __syncthreads();

        const uint32_t stg = sbase + (it & 1) * STAGE_BYTES;
        const uint32_t sA = stg;
        const uint32_t sB = stg + MATA_BYTES;

#pragma unroll
        for (int ks = 0; ks < 4; ks++) {
            const int ca = ks * 2 + a_col8;
            const int cb = ks * 2 + b_col8;
            uint32_t a[4][4], bfr[2][4];
#pragma unroll
            for (int i = 0; i < 4; i++)
                ldsm4(sA + SWO(i * 16 + a_row, ca), a[i]);
#pragma unroll
            for (int j2 = 0; j2 < 2; j2++)
                ldsm4(sB + SWO(wn + j2 * 16 + b_row, cb), bfr[j2]);
#pragma unroll
            for (int i = 0; i < 4; i++)
#pragma unroll
                for (int j = 0; j < 4; j++)
                    mma16816(acc[i][j], a[i], &bfr[j >> 1][(j & 1) * 2]);
        }

        __syncthreads();   // buffer it&1 fully consumed before refill
        if (it + 2 < NK) LOAD_STAGE(it + 2, it & 1);
        asm volatile("cp.async.commit_group;");   // one commit per iter
    }

    asm volatile("cp.async.wait_group 0;");
    __syncthreads();

    // ---- epilogue: four 64-o quarters staged through smem ----
    // stride 68 floats = 272 B = 17*16 -> float4-aligned rows.
    float* eb = (float*)smem;            // [64 o][68 m] floats = 17.4 KB
    const int bidx = m0 >> 10;
    const int pq0  = m0 & 1023;

#pragma unroll
    for (int h = 0; h < 4; h++) {
        const int oh0 = h * 64;
        if (wn >= oh0 && wn < oh0 + 64) {
#pragma unroll
            for (int i = 0; i < 4; i++) {
                int ml = i * 16 + (lane >> 2);
#pragma unroll
                for (int j = 0; j < 4; j++) {
                    int ol = wn - oh0 + j * 8 + (lane & 3) * 2;
                    eb[ol * 68 + ml]           = acc[i][j][0];
                    eb[(ol + 1) * 68 + ml]     = acc[i][j][1];
                    eb[ol * 68 + ml + 8]       = acc[i][j][2];
                    eb[(ol + 1) * 68 + ml + 8] = acc[i][j][3];
                }
            }
        }
        __syncthreads();

        // 256 threads store 64 o x 64 m: 16 floats each
        const int oo   = tid >> 2;           // 0..63
        const int quad = tid & 3;            // 16 m each
        const int og   = oh0 + oo;
        const float bv = __ldg(bias + og);
        float* op = out + (size_t)bidx * (O_ * 1024)
                  + (size_t)og * 1024 + pq0 + quad * 16;
        const float* sp = eb + oo * 68 + quad * 16;
#pragma unroll
        for (int i = 0; i < 4; i++) {
            float4 vv = *(const float4*)(sp + i * 4);
            vv.x += bv; vv.y += bv; vv.z += bv; vv.w += bv;
            *(float4*)(op + i * 4) = vv;
        }
        __syncthreads();
    }
#undef LOAD_STAGE
}

// ---------------------------------------------------------------------------
extern "C" void kernel_launch(void* const* d_in, const int* in_sizes, int n_in,
                              void* d_out, int out_size)
{
    const float* x    = (const float*)d_in[0];
    const float* w    = (const float*)d_in[1];
    const float* bias = (const float*)d_in[2];
    const float* sh   = (const float*)d_in[3];
    const float* sw   = (const float*)d_in[4];
    float* out = (float*)d_out;

    cudaFuncSetAttribute(im2col_kernel,
                         cudaFuncAttributeMaxDynamicSharedMemorySize, IM2COL_SMEM);
    cudaFuncSetAttribute(gemm_kernel,
                         cudaFuncAttributeMaxDynamicSharedMemorySize, SMEM_BYTES);

    im2col_kernel<<<1024, 256, IM2COL_SMEM>>>(x, sh, sw);
    wconv_kernel<<<(O_ * K_) / 256, 256>>>(w);
    gemm_kernel<<<512, 256, SMEM_BYTES>>>(bias, out);
}

// round 17
// speedup vs baseline: 1.5278x; 1.4092x over previous
#include <cuda_runtime.h>
#include <cuda_fp16.h>
#include <cstdint>

// Problem constants
#define B_   32
#define C_   128
#define H_   64
#define W_   64
#define O_   256
#define K_   1152            // C*9
#define M_   32768           // B*32*32

// Static device scratch
__device__ __half g_pa[(size_t)M_ * K_];   // patches fp16, [m][k]
__device__ __half g_wb[O_ * K_];           // weight fp16,  [o][k]

// ---------------------------------------------------------------------------
// Kernel 1: bilinear im2col (blocks 0..1023) + weight convert (blocks >=1024).
//   im2col path is the measured-best R7 form; wconv path overlaps under it.
// ---------------------------------------------------------------------------
#define OUT_STRIDE 292
#define XS_BYTES   32768
#define IM2COL_SMEM (XS_BYTES + 32 * OUT_STRIDE * 2)   // 51456
#define WCONV_BLOCKS ((O_ * K_) / 256)                  // 1152
#define PREP_GRID (1024 + WCONV_BLOCKS)                 // 2176

__global__ __launch_bounds__(256, 4)
void prep_kernel(const float* __restrict__ x,
                 const float* __restrict__ w,
                 const float* __restrict__ sh_p,
                 const float* __restrict__ sw_p)
{
    const int t = threadIdx.x;

    // ---- weight-convert blocks: no smem, no syncs, early return ----
    if (blockIdx.x >= 1024) {
        int idx = (blockIdx.x - 1024) * 256 + t;
        g_wb[idx] = __float2half_rn(w[idx]);
        return;
    }

    extern __shared__ char sm[];
    float* xs = (float*)sm;                              // [c][4][64]
    __half* ohi = (__half*)(sm + XS_BYTES);              // [32][OUT_STRIDE]

    const int b = blockIdx.x >> 5;
    const int p = blockIdx.x & 31;

    const float sh = __ldg(sh_p);
    const float sw = __ldg(sw_p);

    const float ph = (float)p * sh - 1.0f;
    const float fh = floorf(ph);
    const int   h0 = (int)fh;
    const float ah = ph - fh;

    const int q  = t & 31;
    const int cg = t >> 5;
    const float pw = (float)q * sw - 1.0f;
    const float fw = floorf(pw);
    const int   w0 = (int)fw;
    const float aw = pw - fw;

    for (int cc = 0; cc < 4; cc++) {
        const int c0 = cc * 32;

        {
            const float4* xg = (const float4*)x;
            for (int i = t; i < 2048; i += 256) {
                const int cl  = i >> 6;
                const int rem = i & 63;
                const int r   = rem >> 4;
                const int w4  = rem & 15;
                const int hr  = h0 + r;
                float4 v = make_float4(0.f, 0.f, 0.f, 0.f);
                if ((unsigned)hr < (unsigned)H_)
                    v = xg[((size_t)(b * C_ + c0 + cl) * H_ + hr) * 16 + w4];
                ((float4*)xs)[i] = v;
            }
        }
        __syncthreads();

#pragma unroll
        for (int i = 0; i < 4; i++) {
            const int cl = cg * 4 + i;
            const float* xr = xs + cl * 256;

            float v[4][4];
#pragma unroll
            for (int r = 0; r < 4; r++)
#pragma unroll
                for (int j = 0; j < 4; j++) {
                    const int wc = w0 + j;
                    v[r][j] = ((unsigned)wc < (unsigned)W_) ? xr[r * 64 + wc] : 0.0f;
                }

            float cwv[4][3];
#pragma unroll
            for (int r = 0; r < 4; r++)
#pragma unroll
                for (int kw = 0; kw < 3; kw++)
                    cwv[r][kw] = (1.0f - aw) * v[r][kw] + aw * v[r][kw + 1];

            __half* oh = ohi + q * OUT_STRIDE + cl * 9;
#pragma unroll
            for (int kh = 0; kh < 3; kh++)
#pragma unroll
                for (int kw = 0; kw < 3; kw++) {
                    const float val = (1.0f - ah) * cwv[kh][kw] + ah * cwv[kh + 1][kw];
                    oh[kh * 3 + kw] = __float2half_rn(val);
                }
        }
        __syncthreads();

        {
            const size_t mrow = (size_t)(b * 1024 + p * 32);
            for (int i = t; i < 2304; i += 256) {
                const int qq = i / 72;
                const int j  = i - qq * 72;
                const uint2 vh = *(const uint2*)((const char*)ohi + qq * (OUT_STRIDE * 2) + j * 8);
                const size_t gd = ((mrow + qq) * K_ + c0 * 9) * 2 + j * 8;
                *(uint2*)((char*)g_pa + gd) = vh;
            }
        }
        __syncthreads();
    }
}

// ---------------------------------------------------------------------------
// Kernel 2: fp16 GEMM, D[128m x 256n] per CTA (A read ONCE), R10 config,
//   4-stage cp.async pipeline (196 KB smem), single sync per iteration.
//   512 threads, 16 warps = 2(m) x 8(n), warp tile 64m x 32n.
// ---------------------------------------------------------------------------
#define BK 64
#define NK (K_ / BK)              // 18
#define MATA_BYTES (128 * 128)    // 16 KB
#define MATB_BYTES (256 * 128)    // 32 KB
#define STAGE_BYTES (MATA_BYTES + MATB_BYTES)   // 49152
#define NSTAGE 4
#define SMEM_BYTES (NSTAGE * STAGE_BYTES)       // 196608

#define SWO(row, chunk) ((uint32_t)((row) * 128 + (((chunk) ^ ((row) & 7)) << 4)))

__device__ __forceinline__ uint32_t cvta_s(const void* p)
{
    uint32_t a;
    asm("{ .reg .u64 t; cvta.to.shared.u64 t, %1; cvt.u32.u64 %0, t; }"
        : "=r"(a) : "l"(p));
    return a;
}

__device__ __forceinline__ void cp16(uint32_t s, const void* g)
{
    asm volatile("cp.async.ca.shared.global [%0], [%1], 16;"
                 :: "r"(s), "l"(g));
}

__device__ __forceinline__ void ldsm4(uint32_t a, uint32_t* r)
{
    asm volatile("ldmatrix.sync.aligned.m8n8.x4.shared.b16 {%0,%1,%2,%3}, [%4];"
                 : "=r"(r[0]), "=r"(r[1]), "=r"(r[2]), "=r"(r[3]) : "r"(a));
}

__device__ __forceinline__ void mma16816(float* d, const uint32_t* a,
                                         const uint32_t* b)
{
    asm volatile(
        "mma.sync.aligned.m16n8k16.row.col.f32.f16.f16.f32 "
        "{%0,%1,%2,%3}, {%4,%5,%6,%7}, {%8,%9}, {%0,%1,%2,%3};"
        : "+f"(d[0]), "+f"(d[1]), "+f"(d[2]), "+f"(d[3])
        : "r"(a[0]), "r"(a[1]), "r"(a[2]), "r"(a[3]), "r"(b[0]), "r"(b[1]));
}

__global__ __launch_bounds__(512, 1)
void gemm_kernel(const float* __restrict__ bias, float* __restrict__ out)
{
    extern __shared__ char smem[];
    const uint32_t sbase = cvta_s(smem);

    const int tid  = threadIdx.x;
    const int lane = tid & 31;
    const int wid  = tid >> 5;
    const int m0   = blockIdx.x * 128;

    // loader: per stage A=1024 chunks (2/thr), B=2048 chunks (4/thr)
    const int rowA = tid >> 2;                 // 0..127
    const int cA0  = (tid & 3) * 2;            // 2 chunks
    const int rowB = tid >> 1;                 // 0..255
    const int cB0  = (tid & 1) * 4;            // 4 chunks
    const char* gA = (const char*)g_pa + ((size_t)(m0 + rowA) * K_) * 2;
    const char* gB = (const char*)g_wb + ((size_t)rowB * K_) * 2;

#define LOAD_STAGE(stage, buf)                                                 \
    {                                                                          \
        const uint32_t sbA = sbase + (buf) * STAGE_BYTES;                      \
        const uint32_t sbB = sbA + MATA_BYTES;                                 \
        const size_t gk = (size_t)(stage) * 128;                               \
        _Pragma("unroll")                                                      \
        for (int ci = 0; ci < 2; ci++)                                         \
            cp16(sbA + SWO(rowA, cA0 + ci), gA + gk + (cA0 + ci) * 16);        \
        _Pragma("unroll")                                                      \
        for (int ci = 0; ci < 4; ci++)                                         \
            cp16(sbB + SWO(rowB, cB0 + ci), gB + gk + (cB0 + ci) * 16);        \
    }

    // warp grid: 2 (m) x 8 (n); warp tile 64m x 32n
    const int wm = (wid & 1) * 64;
    const int wn = (wid >> 1) * 32;

    const int a_row  = lane & 15;
    const int a_col8 = lane >> 4;
    const int b_row  = (lane & 7) + ((lane >> 4) << 3);
    const int b_col8 = (lane >> 3) & 1;

    float acc[4][4][4];
#pragma unroll
    for (int i = 0; i < 4; i++)
#pragma unroll
        for (int j = 0; j < 4; j++)
#pragma unroll
            for (int r = 0; r < 4; r++) acc[i][j][r] = 0.0f;

    LOAD_STAGE(0, 0);
    asm volatile("cp.async.commit_group;");
    LOAD_STAGE(1, 1);
    asm volatile("cp.async.commit_group;");
    LOAD_STAGE(2, 2);
    asm volatile("cp.async.commit_group;");

    for (int it = 0; it < NK; it++) {
        asm volatile("cp.async.wait_group 2;");
        __syncthreads();

        // refill buffer (it+3)%4 == (it-1)%4: all warps passed the sync above,
        // so iteration it-1's reads of that buffer are complete.
        if (it + 3 < NK) LOAD_STAGE(it + 3, (it + 3) % NSTAGE);
        asm volatile("cp.async.commit_group;");   // exactly one commit per iter

        const uint32_t stg = sbase + (it % NSTAGE) * STAGE_BYTES;
        const uint32_t sA = stg;
        const uint32_t sB = stg + MATA_BYTES;

#pragma unroll
        for (int ks = 0; ks < 4; ks++) {
            const int ca = ks * 2 + a_col8;
            const int cb = ks * 2 + b_col8;
            uint32_t a[4][4], bfr[2][4];
#pragma unroll
            for (int i = 0; i < 4; i++)
                ldsm4(sA + SWO(wm + i * 16 + a_row, ca), a[i]);
#pragma unroll
            for (int j2 = 0; j2 < 2; j2++)
                ldsm4(sB + SWO(wn + j2 * 16 + b_row, cb), bfr[j2]);
#pragma unroll
            for (int i = 0; i < 4; i++)
#pragma unroll
                for (int j = 0; j < 4; j++)
                    mma16816(acc[i][j], a[i], &bfr[j >> 1][(j & 1) * 2]);
        }
    }

    asm volatile("cp.async.wait_group 0;");
    __syncthreads();

    // ---- epilogue: four 64-o quarters staged through smem ----
    // stride 132 floats = 528 B = 33*16 -> float4-aligned rows.
    float* eb = (float*)smem;            // [64 o][132 m] floats = 33.8 KB
    const int bidx = m0 >> 10;
    const int pq0  = m0 & 1023;

#pragma unroll
    for (int h = 0; h < 4; h++) {
        const int oh0 = h * 64;
        if (wn >= oh0 && wn < oh0 + 64) {
#pragma unroll
            for (int i = 0; i < 4; i++) {
                int ml = wm + i * 16 + (lane >> 2);
#pragma unroll
                for (int j = 0; j < 4; j++) {
                    int ol = wn - oh0 + j * 8 + (lane & 3) * 2;
                    eb[ol * 132 + ml]           = acc[i][j][0];
                    eb[(ol + 1) * 132 + ml]     = acc[i][j][1];
                    eb[ol * 132 + ml + 8]       = acc[i][j][2];
                    eb[(ol + 1) * 132 + ml + 8] = acc[i][j][3];
                }
            }
        }
        __syncthreads();

        // 512 threads store 64 o x 128 m: 16 floats each
        const int oo  = tid >> 3;            // 0..63
        const int oct = tid & 7;             // 16 m each
        const int og  = oh0 + oo;
        const float bv = __ldg(bias + og);
        float* op = out + (size_t)bidx * (O_ * 1024)
                  + (size_t)og * 1024 + pq0 + oct * 16;
        const float* sp = eb + oo * 132 + oct * 16;
#pragma unroll
        for (int i = 0; i < 4; i++) {
            float4 vv = *(const float4*)(sp + i * 4);
            vv.x += bv; vv.y += bv; vv.z += bv; vv.w += bv;
            *(float4*)(op + i * 4) = vv;
        }
        __syncthreads();
    }
#undef LOAD_STAGE
}

// ---------------------------------------------------------------------------
extern "C" void kernel_launch(void* const* d_in, const int* in_sizes, int n_in,
                              void* d_out, int out_size)
{
    const float* x    = (const float*)d_in[0];
    const float* w    = (const float*)d_in[1];
    const float* bias = (const float*)d_in[2];
    const float* sh   = (const float*)d_in[3];
    const float* sw   = (const float*)d_in[4];
    float* out = (float*)d_out;

    cudaFuncSetAttribute(prep_kernel,
                         cudaFuncAttributeMaxDynamicSharedMemorySize, IM2COL_SMEM);
    cudaFuncSetAttribute(gemm_kernel,
                         cudaFuncAttributeMaxDynamicSharedMemorySize, SMEM_BYTES);

    prep_kernel<<<PREP_GRID, 256, IM2COL_SMEM>>>(x, w, sh, sw);
    gemm_kernel<<<256, 512, SMEM_BYTES>>>(bias, out);
}